// round 13
// baseline (speedup 1.0000x reference)
#include <cuda_runtime.h>
#include <cstdint>
#include <math.h>

#define EMBED   2048
#define NEXP    64
#define TOPK    8
#define BM      64
#define BK      32
#define NCHUNK  (EMBED / BK)      // 64
#define STAGE_F 4096              // floats/stage: A 2048 + B 2048
#define BOFF    2048              // B offset within stage (floats)

typedef unsigned long long ull;

__device__ __forceinline__ uint32_t smem_u32(const void* p) {
    uint32_t a;
    asm("{ .reg .u64 t; cvta.to.shared.u64 t, %1; cvt.u32.u64 %0, t; }" : "=r"(a) : "l"(p));
    return a;
}
// packed dual-fp32 FMA (Blackwell f32x2 pipe, full fp32 per lane)
__device__ __forceinline__ void fma2(ull& c, ull a, ull b) {
    asm("fma.rn.f32x2 %0, %1, %2, %0;" : "+l"(c) : "l"(a), "l"(b));
}
__device__ __forceinline__ void cpa8(uint32_t dst, const void* src) {
    asm volatile("cp.async.ca.shared.global [%0], [%1], 8;" :: "r"(dst), "l"(src));
}
__device__ __forceinline__ float accf(ull v) {   // lo + hi halves
    return __uint_as_float((uint32_t)v) + __uint_as_float((uint32_t)(v >> 32));
}

__global__ __launch_bounds__(256, 4)
void router_f32x2(const float* __restrict__ X,
                  const float* __restrict__ W,
                  const float* __restrict__ bias,
                  float* __restrict__ out,
                  int M, int write_idx)
{
    __shared__ float sm[2 * STAGE_F];      // 32 KB; reused for scores after mainloop
    const uint32_t smb = smem_u32(sm);
    const int tid = threadIdx.x;
    const int m0  = blockIdx.x * BM;
    const int tg  = tid >> 5;              // warp-uniform: tokens tg*8 .. +7
    const int eg  = tid & 31;              // experts 2*eg, 2*eg+1

    // ---- producer: 2 base pointers + immediate offsets ----
    // A layout: [t][k] linear, token row = 32 floats (128B). STS conflict-free.
    // B layout: [p][e] 16B units, unit u holds experts (2u,2u+1), swizzled u^(p&7).
    // j-step folds to immediates: src += j*16*EMBED; A dst += j*2048B (16 tokens x 128B);
    // B dst += j*128B (16 experts = 8 units x 16B; XOR commutes since pq&7 < 8).
    const int t0 = tid >> 4;               // 0..15
    const int pq = tid & 15;               // k-pair group
    const float* xp = X + (size_t)(m0 + t0) * EMBED + pq * 2;
    const float* wp = W + (size_t)t0 * EMBED + pq * 2;
    const uint32_t adst0 = (uint32_t)(t0 * 32 + pq * 2) * 4;
    const uint32_t bdst0 = (uint32_t)(BOFF + pq * 128 + (((t0 >> 1) ^ (pq & 7)) * 4) + (t0 & 1) * 2) * 4;

    auto issue = [&](int c, int s) {
        const int k0 = c * BK;
        const uint32_t sb = smb + s * (STAGE_F * 4);
        #pragma unroll
        for (int j = 0; j < 4; j++)        // A: tokens t0 + 16j
            cpa8(sb + adst0 + j * 2048u, xp + (size_t)j * 16 * EMBED + k0);
        #pragma unroll
        for (int j = 0; j < 4; j++)        // B: experts t0 + 16j (8 units = 128B per step)
            cpa8(sb + bdst0 + j * 128u, wp + (size_t)j * 16 * EMBED + k0);
    };

    ull acc[8][2];
    #pragma unroll
    for (int i = 0; i < 8; i++) { acc[i][0] = 0ull; acc[i][1] = 0ull; }

    issue(0, 0);
    asm volatile("cp.async.commit_group;");

    for (int c = 0; c < NCHUNK; c++) {
        if (c + 1 < NCHUNK) {
            issue(c + 1, (c + 1) & 1);
            asm volatile("cp.async.commit_group;");
            asm volatile("cp.async.wait_group 1;");
        } else {
            asm volatile("cp.async.wait_group 0;");
        }
        __syncthreads();                   // stage c visible

        const float* Ab = sm + (c & 1) * STAGE_F + tg * 256;   // warp's 8 token rows
        const float* Bb = sm + (c & 1) * STAGE_F + BOFF;
        #pragma unroll
        for (int pp = 0; pp < 8; pp++) {   // 2 k-pairs per step
            // B: two conflict-free LDS.128 (lane permutation within 512B row)
            const ulonglong2 bu0 = *(const ulonglong2*)(Bb + (2 * pp)     * 128 + ((eg ^ ((2 * pp)     & 7)) * 4));
            const ulonglong2 bu1 = *(const ulonglong2*)(Bb + (2 * pp + 1) * 128 + ((eg ^ ((2 * pp + 1) & 7)) * 4));
            #pragma unroll
            for (int tt = 0; tt < 8; tt++) {
                // broadcast LDS.128: pairs 2pp (au.x) and 2pp+1 (au.y) of token tt
                const ulonglong2 au = *(const ulonglong2*)(Ab + tt * 32 + pp * 4);
                fma2(acc[tt][0], au.x, bu0.x);   // exp 2eg,   pair 2pp
                fma2(acc[tt][1], au.x, bu0.y);   // exp 2eg+1, pair 2pp
                fma2(acc[tt][0], au.y, bu1.x);   // exp 2eg,   pair 2pp+1
                fma2(acc[tt][1], au.y, bu1.y);   // exp 2eg+1, pair 2pp+1
            }
        }
        __syncthreads();                   // stage c consumed; next issue may overwrite
    }

    // ---------- stage scores (row stride 68) ----------
    #pragma unroll
    for (int tt = 0; tt < 8; tt++) {
        float2 v;
        v.x = accf(acc[tt][0]);            // expert 2*eg
        v.y = accf(acc[tt][1]);            // expert 2*eg+1
        *(float2*)(sm + (tg * 8 + tt) * 68 + eg * 2) = v;
    }
    if (tid < NEXP) sm[4400 + tid] = bias[tid];
    __syncthreads();

    // ---------- per-token top-8 + masked softmax (verified R1/R8-R10) ----------
    if (tid < BM) {
        const int r = tid;
        float sc[64];
        #pragma unroll
        for (int jj = 0; jj < 16; jj++) {
            float4 v  = *(const float4*)(sm + r * 68 + jj * 4);
            float4 bv = *(const float4*)(sm + 4400 + jj * 4);
            sc[jj * 4 + 0] = v.x + bv.x;
            sc[jj * 4 + 1] = v.y + bv.y;
            sc[jj * 4 + 2] = v.z + bv.z;
            sc[jj * 4 + 3] = v.w + bv.w;
        }

        float vals[TOPK];
        int   idxs[TOPK];
        #pragma unroll
        for (int i = 0; i < TOPK; i++) { vals[i] = -INFINITY; idxs[i] = 0; }
        #pragma unroll
        for (int j = 0; j < NEXP; j++) {
            float s = sc[j];
            if (s > vals[TOPK - 1]) {            // strict > : ties keep lower index
                vals[TOPK - 1] = s; idxs[TOPK - 1] = j;
                #pragma unroll
                for (int q = TOPK - 1; q > 0; q--) {
                    if (vals[q] > vals[q - 1]) {
                        float tv = vals[q]; vals[q] = vals[q - 1]; vals[q - 1] = tv;
                        int   ti = idxs[q]; idxs[q] = idxs[q - 1]; idxs[q - 1] = ti;
                    }
                }
            }
        }

        const float mx   = fmaxf(vals[0], 0.f);
        const float base = expf(-mx);
        float den = (float)(NEXP - TOPK) * base;
        float ev[TOPK];
        #pragma unroll
        for (int i = 0; i < TOPK; i++) { ev[i] = expf(vals[i] - mx); den += ev[i]; }
        const float inv = 1.f / den;
        const float bz  = base * inv;

        const int token = m0 + r;
        float* orow = out + (size_t)token * NEXP;
        #pragma unroll
        for (int j = 0; j < NEXP; j += 4) {
            float4 v; v.x = bz; v.y = bz; v.z = bz; v.w = bz;
            *(float4*)(orow + j) = v;
        }
        #pragma unroll
        for (int i = 0; i < TOPK; i++)
            orow[idxs[i]] = ev[i] * inv;

        if (write_idx) {
            float* oi = out + (size_t)M * NEXP + (size_t)token * TOPK;
            #pragma unroll
            for (int i = 0; i < TOPK; i++) oi[i] = (float)idxs[i];
        }
    }
}

extern "C" void kernel_launch(void* const* d_in, const int* in_sizes, int n_in,
                              void* d_out, int out_size) {
    const float* X = (const float*)d_in[0];
    const float* W = (const float*)d_in[1];
    const float* b = (const float*)d_in[2];
    int M = in_sizes[0] / EMBED;                        // 32768 tokens
    int write_idx = (out_size >= M * (NEXP + TOPK)) ? 1 : 0;
    router_f32x2<<<M / BM, 256>>>(X, W, b, (float*)d_out, M, write_idx);
}

// round 14
// speedup vs baseline: 1.0850x; 1.0850x over previous
#include <cuda_runtime.h>
#include <cstdint>
#include <math.h>

#define EMBED   2048
#define NEXP    64
#define TOPK    8
#define BM      128
#define BK      32
#define NCHUNK  (EMBED / BK)      // 64
#define STAGE_F 6144              // floats/stage: A 4096 + B 2048
#define BOFF    4096              // B offset within stage (floats)
#define NSTAGE  4
#define SMEM_BYTES (NSTAGE * STAGE_F * 4)   // 98304

typedef unsigned long long ull;

__device__ __forceinline__ uint32_t smem_u32(const void* p) {
    uint32_t a;
    asm("{ .reg .u64 t; cvta.to.shared.u64 t, %1; cvt.u32.u64 %0, t; }" : "=r"(a) : "l"(p));
    return a;
}
// packed dual-fp32 FMA (Blackwell f32x2 pipe, full fp32 per lane)
__device__ __forceinline__ void fma2(ull& c, ull a, ull b) {
    asm("fma.rn.f32x2 %0, %1, %2, %0;" : "+l"(c) : "l"(a), "l"(b));
}
__device__ __forceinline__ void cpa8(uint32_t dst, const void* src) {
    asm volatile("cp.async.ca.shared.global [%0], [%1], 8;" :: "r"(dst), "l"(src));
}
__device__ __forceinline__ float accf(ull v) {   // lo + hi halves
    return __uint_as_float((uint32_t)v) + __uint_as_float((uint32_t)(v >> 32));
}

__global__ __launch_bounds__(256, 2)
void router_f32x2(const float* __restrict__ X,
                  const float* __restrict__ W,
                  const float* __restrict__ bias,
                  float* __restrict__ out,
                  int M, int write_idx)
{
    extern __shared__ float sm[];          // 96 KB: 4 stages; reused for scores
    const uint32_t smb = smem_u32(sm);
    const int tid = threadIdx.x;
    const int m0  = blockIdx.x * BM;
    const int tg  = tid >> 5;              // warp-uniform: tokens tg*16 .. +15
    const int eg  = tid & 31;              // experts 2*eg, 2*eg+1

    // ---- hoisted producer addressing (R10-verified) ----
    // A layout: [t][k] linear, token row = 32 floats (128B). STS conflict-free.
    // B layout: [p][e] 16B units, unit u holds experts (2u,2u+1), swizzled u^(p&7).
    const float* xsrc[8]; uint32_t adst[8];
    #pragma unroll
    for (int j = 0; j < 8; j++) {
        const int ci = tid + j * 256;      // 0..2047
        const int t = ci >> 4, p = ci & 15;
        xsrc[j] = X + (size_t)(m0 + t) * EMBED + p * 2;
        adst[j] = (uint32_t)(t * 32 + p * 2) * 4;
    }
    const float* wsrc[4]; uint32_t bdst[4];
    #pragma unroll
    for (int j = 0; j < 4; j++) {
        const int ci = tid + j * 256;      // 0..1023
        const int e = ci >> 4, p = ci & 15;
        wsrc[j] = W + (size_t)e * EMBED + p * 2;
        bdst[j] = (uint32_t)(BOFF + p * 128 + (((e >> 1) ^ (p & 7)) * 4) + (e & 1) * 2) * 4;
    }

    auto issue = [&](int c) {
        const int k0 = c * BK;
        const uint32_t sb = smb + (uint32_t)(c & 3) * (STAGE_F * 4);
        #pragma unroll
        for (int j = 0; j < 8; j++) cpa8(sb + adst[j], xsrc[j] + k0);
        #pragma unroll
        for (int j = 0; j < 4; j++) cpa8(sb + bdst[j], wsrc[j] + k0);
    };

    ull acc[16][2];
    #pragma unroll
    for (int i = 0; i < 16; i++) { acc[i][0] = 0ull; acc[i][1] = 0ull; }

    // prologue: chunks 0,1,2 in flight (stages 0,1,2)
    issue(0); asm volatile("cp.async.commit_group;");
    issue(1); asm volatile("cp.async.commit_group;");
    issue(2); asm volatile("cp.async.commit_group;");

    for (int c = 0; c < NCHUNK; c++) {
        // issue(c+2) targets stage (c+2)&3 == (c-2)&3; its last reader (chunk c-2)
        // finished before the PREVIOUS iteration's barrier -> safe to overwrite.
        if (c > 0 && c + 2 < NCHUNK) {
            issue(c + 2);
            asm volatile("cp.async.commit_group;");
        }
        // pending groups ⊆ {c, c+1, c+2}; ensure chunk c's data landed (this thread)
        if (c + 2 < NCHUNK)      asm volatile("cp.async.wait_group 2;");
        else if (c + 1 < NCHUNK) asm volatile("cp.async.wait_group 1;");
        else                     asm volatile("cp.async.wait_group 0;");
        __syncthreads();                   // all warps waited -> stage c visible to all

        const float* Ab = sm + (c & 3) * STAGE_F + tg * 512;   // warp's 16 token rows
        const float* Bb = sm + (c & 3) * STAGE_F + BOFF;
        #pragma unroll
        for (int pp = 0; pp < 8; pp++) {   // 2 k-pairs per step
            // B: two conflict-free LDS.128 (lane permutation within 512B row)
            const ulonglong2 bu0 = *(const ulonglong2*)(Bb + (2 * pp)     * 128 + ((eg ^ ((2 * pp)     & 7)) * 4));
            const ulonglong2 bu1 = *(const ulonglong2*)(Bb + (2 * pp + 1) * 128 + ((eg ^ ((2 * pp + 1) & 7)) * 4));
            #pragma unroll
            for (int tt = 0; tt < 16; tt++) {
                // broadcast LDS.128: pairs 2pp (au.x) and 2pp+1 (au.y) of token tt
                const ulonglong2 au = *(const ulonglong2*)(Ab + tt * 32 + pp * 4);
                fma2(acc[tt][0], au.x, bu0.x);   // exp 2eg,   pair 2pp
                fma2(acc[tt][1], au.x, bu0.y);   // exp 2eg+1, pair 2pp
                fma2(acc[tt][0], au.y, bu1.x);   // exp 2eg,   pair 2pp+1
                fma2(acc[tt][1], au.y, bu1.y);   // exp 2eg+1, pair 2pp+1
            }
        }
    }
    __syncthreads();                       // all warps done with final stage

    // ---------- stage scores (row stride 68; region [0,8768) is dead stage data) ----------
    #pragma unroll
    for (int tt = 0; tt < 16; tt++) {
        float2 v;
        v.x = accf(acc[tt][0]);            // expert 2*eg
        v.y = accf(acc[tt][1]);            // expert 2*eg+1
        *(float2*)(sm + (tg * 16 + tt) * 68 + eg * 2) = v;
    }
    if (tid < NEXP) sm[8704 + tid] = bias[tid];
    __syncthreads();

    // ---------- per-token top-8 + masked softmax (verified R1/R8-R13) ----------
    if (tid < BM) {
        const int r = tid;
        float sc[64];
        #pragma unroll
        for (int jj = 0; jj < 16; jj++) {
            float4 v  = *(const float4*)(sm + r * 68 + jj * 4);
            float4 bv = *(const float4*)(sm + 8704 + jj * 4);
            sc[jj * 4 + 0] = v.x + bv.x;
            sc[jj * 4 + 1] = v.y + bv.y;
            sc[jj * 4 + 2] = v.z + bv.z;
            sc[jj * 4 + 3] = v.w + bv.w;
        }

        float vals[TOPK];
        int   idxs[TOPK];
        #pragma unroll
        for (int i = 0; i < TOPK; i++) { vals[i] = -INFINITY; idxs[i] = 0; }
        #pragma unroll
        for (int j = 0; j < NEXP; j++) {
            float s = sc[j];
            if (s > vals[TOPK - 1]) {            // strict > : ties keep lower index
                vals[TOPK - 1] = s; idxs[TOPK - 1] = j;
                #pragma unroll
                for (int q = TOPK - 1; q > 0; q--) {
                    if (vals[q] > vals[q - 1]) {
                        float tv = vals[q]; vals[q] = vals[q - 1]; vals[q - 1] = tv;
                        int   ti = idxs[q]; idxs[q] = idxs[q - 1]; idxs[q - 1] = ti;
                    }
                }
            }
        }

        const float mx   = fmaxf(vals[0], 0.f);
        const float base = expf(-mx);
        float den = (float)(NEXP - TOPK) * base;
        float ev[TOPK];
        #pragma unroll
        for (int i = 0; i < TOPK; i++) { ev[i] = expf(vals[i] - mx); den += ev[i]; }
        const float inv = 1.f / den;
        const float bz  = base * inv;

        const int token = m0 + r;
        float* orow = out + (size_t)token * NEXP;
        #pragma unroll
        for (int j = 0; j < NEXP; j += 4) {
            float4 v; v.x = bz; v.y = bz; v.z = bz; v.w = bz;
            *(float4*)(orow + j) = v;
        }
        #pragma unroll
        for (int i = 0; i < TOPK; i++)
            orow[idxs[i]] = ev[i] * inv;

        if (write_idx) {
            float* oi = out + (size_t)M * NEXP + (size_t)token * TOPK;
            #pragma unroll
            for (int i = 0; i < TOPK; i++) oi[i] = (float)idxs[i];
        }
    }
}

extern "C" void kernel_launch(void* const* d_in, const int* in_sizes, int n_in,
                              void* d_out, int out_size) {
    const float* X = (const float*)d_in[0];
    const float* W = (const float*)d_in[1];
    const float* b = (const float*)d_in[2];
    int M = in_sizes[0] / EMBED;                        // 32768 tokens
    int write_idx = (out_size >= M * (NEXP + TOPK)) ? 1 : 0;

    cudaFuncSetAttribute(router_f32x2, cudaFuncAttributeMaxDynamicSharedMemorySize, SMEM_BYTES);
    router_f32x2<<<M / BM, 256, SMEM_BYTES>>>(X, W, b, (float*)d_out, M, write_idx);
}